// round 12
// baseline (speedup 1.0000x reference)
#include <cuda_runtime.h>
#include <cuda_bf16.h>

// Problem constants
#define B 4
#define L 512
#define E 1024
#define H 128
#define NR (B * L)          // 2048 rows per tensor

__device__ __align__(16) float g_hid[2 * NR * H];
__device__ unsigned g_maxu[B];
__device__ int g_done;

typedef unsigned long long ull;

__device__ __forceinline__ float tanh_ap(float x) {
    float y;
    asm("tanh.approx.f32 %0, %1;" : "=f"(y) : "f"(x));
    return y;
}
__device__ __forceinline__ ull pack2(float lo, float hi) {
    ull r; asm("mov.b64 %0, {%1, %2};" : "=l"(r) : "f"(lo), "f"(hi)); return r;
}
__device__ __forceinline__ void unpack2(ull v, float& lo, float& hi) {
    asm("mov.b64 {%0, %1}, %2;" : "=f"(lo), "=f"(hi) : "l"(v));
}
__device__ __forceinline__ ull mul2(ull a, ull b) {
    ull r; asm("mul.rn.f32x2 %0, %1, %2;" : "=l"(r) : "l"(a), "l"(b)); return r;
}
__device__ __forceinline__ ull fma2(ull a, ull b, ull c) {
    ull r; asm("fma.rn.f32x2 %0, %1, %2, %3;" : "=l"(r) : "l"(a), "l"(b), "l"(c)); return r;
}
__device__ __forceinline__ unsigned tf32r(float x) {
    unsigned u;
    asm("cvt.rna.tf32.f32 %0, %1;" : "=r"(u) : "f"(x));
    return u;
}

__device__ __forceinline__ unsigned fenc(float f) {
    unsigned b = __float_as_uint(f);
    return (b & 0x80000000u) ? ~b : (b | 0x80000000u);
}
__device__ __forceinline__ float fdec(unsigned u) {
    return (u & 0x80000000u) ? __uint_as_float(u & 0x7fffffffu)
                             : __uint_as_float(~u);
}

// m16n8k8 tf32 MMA, f32 accumulate
__device__ __forceinline__ void mma_tf32(float c[4], const unsigned a[4],
                                         const unsigned b[2]) {
    asm volatile(
        "mma.sync.aligned.m16n8k8.row.col.f32.tf32.tf32.f32 "
        "{%0,%1,%2,%3}, {%4,%5,%6,%7}, {%8,%9}, {%0,%1,%2,%3};"
        : "+f"(c[0]), "+f"(c[1]), "+f"(c[2]), "+f"(c[3])
        : "r"(a[0]), "r"(a[1]), "r"(a[2]), "r"(a[3]),
          "r"(b[0]), "r"(b[1]));
}

// ---------------------------------------------------------------------------
// Kernel 1: hid = relu(emb @ W1 + b1) on the tensor pipe (tf32 mma.sync).
// (Unchanged — proven.)
// ---------------------------------------------------------------------------
#define KC 32
#define NTK (E / KC)     // 32 tiles
#define APAD 36
#define WPAD 72

__global__ __launch_bounds__(256) void gemm_tc_kernel(
    const float* __restrict__ rec, const float* __restrict__ lig,
    const float* __restrict__ W1, const float* __restrict__ b1)
{
    __shared__ __align__(16) float A_s[2][64][APAD];
    __shared__ __align__(16) float W_s[2][KC][WPAD];

    const int t    = threadIdx.x;
    const int bx   = blockIdx.x;
    const int row0 = (bx >> 1) * 64;
    const int col0 = (bx & 1) * 64;

    if (bx == 0 && t == 0) {
        g_done = 0;
#pragma unroll
        for (int b = 0; b < B; ++b) g_maxu[b] = 0u;
    }

    const int wid  = t >> 5;
    const int lane = t & 31;
    const int qr   = lane >> 2;        // 0..7
    const int qk   = lane & 3;         // 0..3
    const int wr   = (wid >> 2) * 32;
    const int wc   = (wid & 3) * 16;

    const int lar = t >> 2, lak = (t & 3) * 8;
    const float* aptr;
    {
        int gr = row0 + lar;
        aptr = (gr < NR) ? (rec + (size_t)gr * E + lak)
                         : (lig + (size_t)(gr - NR) * E + lak);
    }
    const int lwk = t >> 3, lwn = (t & 7) * 8;
    const float* wptr = W1 + (size_t)lwk * H + col0 + lwn;

    float4 aR0, aR1, wR0, wR1;
    float c[2][2][4];
#pragma unroll
    for (int m = 0; m < 2; ++m)
#pragma unroll
        for (int n = 0; n < 2; ++n)
#pragma unroll
            for (int i = 0; i < 4; ++i) c[m][n][i] = 0.f;

#define LDG_TILE(k0)                                         \
    {                                                        \
        aR0 = *(const float4*)(aptr + (k0));                 \
        aR1 = *(const float4*)(aptr + (k0) + 4);             \
        wR0 = *(const float4*)(wptr + (size_t)(k0) * H);     \
        wR1 = *(const float4*)(wptr + (size_t)(k0) * H + 4); \
    }
#define STS_TILE(buf)                                                     \
    {                                                                     \
        uint4 ua0 = make_uint4(tf32r(aR0.x), tf32r(aR0.y),                \
                               tf32r(aR0.z), tf32r(aR0.w));               \
        uint4 ua1 = make_uint4(tf32r(aR1.x), tf32r(aR1.y),                \
                               tf32r(aR1.z), tf32r(aR1.w));               \
        uint4 uw0 = make_uint4(tf32r(wR0.x), tf32r(wR0.y),                \
                               tf32r(wR0.z), tf32r(wR0.w));               \
        uint4 uw1 = make_uint4(tf32r(wR1.x), tf32r(wR1.y),                \
                               tf32r(wR1.z), tf32r(wR1.w));               \
        *(uint4*)&A_s[buf][lar][lak]     = ua0;                           \
        *(uint4*)&A_s[buf][lar][lak + 4] = ua1;                           \
        *(uint4*)&W_s[buf][lwk][lwn]     = uw0;                           \
        *(uint4*)&W_s[buf][lwk][lwn + 4] = uw1;                           \
    }

    LDG_TILE(0);
    STS_TILE(0);
    LDG_TILE(KC);
    __syncthreads();

    for (int kt = 0; kt < NTK; ++kt) {
        int cur = kt & 1;
#pragma unroll
        for (int ks = 0; ks < KC / 8; ++ks) {
            int k0 = ks * 8;
            unsigned a[2][4], bb[2][2];
#pragma unroll
            for (int m = 0; m < 2; ++m) {
                int r = wr + m * 16 + qr;
                a[m][0] = __float_as_uint(A_s[cur][r][k0 + qk]);
                a[m][1] = __float_as_uint(A_s[cur][r + 8][k0 + qk]);
                a[m][2] = __float_as_uint(A_s[cur][r][k0 + qk + 4]);
                a[m][3] = __float_as_uint(A_s[cur][r + 8][k0 + qk + 4]);
            }
#pragma unroll
            for (int n = 0; n < 2; ++n) {
                int nn = wc + n * 8 + qr;
                bb[n][0] = __float_as_uint(W_s[cur][k0 + qk][nn]);
                bb[n][1] = __float_as_uint(W_s[cur][k0 + qk + 4][nn]);
            }
            mma_tf32(c[0][0], a[0], bb[0]);
            mma_tf32(c[0][1], a[0], bb[1]);
            mma_tf32(c[1][0], a[1], bb[0]);
            mma_tf32(c[1][1], a[1], bb[1]);
        }
        if (kt + 1 < NTK) {
            STS_TILE(cur ^ 1);
            if (kt + 2 < NTK) LDG_TILE((kt + 2) * KC);
        }
        __syncthreads();
    }

#pragma unroll
    for (int m = 0; m < 2; ++m) {
#pragma unroll
        for (int n = 0; n < 2; ++n) {
            int row = row0 + wr + m * 16 + qr;
            int col = col0 + wc + n * 8 + 2 * qk;
            float2 bv = *(const float2*)(b1 + col);
            float2 o0, o1;
            o0.x = fmaxf(c[m][n][0] + bv.x, 0.f);
            o0.y = fmaxf(c[m][n][1] + bv.y, 0.f);
            o1.x = fmaxf(c[m][n][2] + bv.x, 0.f);
            o1.y = fmaxf(c[m][n][3] + bv.y, 0.f);
            *(float2*)&g_hid[(size_t)row * H + col]       = o0;
            *(float2*)&g_hid[(size_t)(row + 8) * H + col] = o1;
        }
    }
}

// ---------------------------------------------------------------------------
// Kernel 2: back to the R9 shape (32x32 S-tile, 2x2 micro-tile, 16x16 thr),
// but with an h2-step inner loop (half the live R/L/W registers) and
// __launch_bounds__(256, 4) to get 4 blocks/SM (occ 32% -> 50%) so the
// MUFU (tanh) pipe stays saturated.
// ---------------------------------------------------------------------------
#define TS 31
#define NTILE ((L + TS - 1) / TS)            // 17
#define NBLK  (NTILE * NTILE * B)            // 1156
#define LPAD 132

__global__ __launch_bounds__(256, 4) void tile_max_kernel(
    const float* __restrict__ conv_w, const float* __restrict__ conv_b,
    float* __restrict__ out)
{
    __shared__ __align__(16) float r_s[32][LPAD];   // 16896 B (aliased by S)
    __shared__ __align__(16) float l_s[32][LPAD];   // 16896 B
    __shared__ __align__(16) float4 w4_s[H];        // 2 KB

    const int tx = threadIdx.x;          // 0..15
    const int ty = threadIdx.y;          // 0..15
    const int t  = ty * 16 + tx;
    const int b  = blockIdx.z;
    const int i0 = blockIdx.y * TS;
    const int j0 = blockIdx.x * TS;

    {
        int lr  = t >> 3;          // 0..31 row
        int lc4 = t & 7;           // base float4 col
        int iload = i0 - 1 + lr;
        int jload = j0 - 1 + lr;
        const float4* rsrc = (const float4*)(g_hid + (size_t)(b * L + iload) * H);
        const float4* lsrc = (const float4*)(g_hid + (size_t)(NR + b * L + jload) * H);
        bool rok = (iload >= 0 && iload < L);
        bool lok = (jload >= 0 && jload < L);
        float4 zz = make_float4(0.f, 0.f, 0.f, 0.f);
        float4* rdst = (float4*)&r_s[lr][0];
        float4* ldst = (float4*)&l_s[lr][0];
#pragma unroll
        for (int k = 0; k < 4; ++k) {
            int c4 = lc4 + 8 * k;
            rdst[c4] = rok ? rsrc[c4] : zz;
            ldst[c4] = lok ? lsrc[c4] : zz;
        }
        if (t < H) w4_s[t] = ((const float4*)conv_w)[t];   // (w00,w01,w10,w11)
    }
    __syncthreads();

    ull a00A = 0, a00B = 0, a01A = 0, a01B = 0;
    ull a10A = 0, a10B = 0, a11A = 0, a11B = 0;
    const ull* rp0 = (const ull*)&r_s[ty][0];
    const ull* rp1 = (const ull*)&r_s[ty + 16][0];
    const ull* lp0 = (const ull*)&l_s[tx][0];
    const ull* lp1 = (const ull*)&l_s[tx + 16][0];
    const ulonglong2* wq = (const ulonglong2*)&w4_s[0];   // wq[h] = taps of h

    // One h2 step = 2 h values; W0/W1 are each h's (w00,w01 | w10,w11) pairs.
#define COMBO2(Rv, Lv, AA, BB)                                             \
    {                                                                      \
        ull pA = mul2(Rv, Lv);                                             \
        float x0, x1;                                                      \
        unpack2(pA, x0, x1);                                               \
        float t0 = tanh_ap(x0), t1 = tanh_ap(x1);                          \
        ull T0 = pack2(t0, t0), T1 = pack2(t1, t1);                        \
        AA = fma2(T0, W0.x, AA); BB = fma2(T0, W0.y, BB);                  \
        AA = fma2(T1, W1.x, AA); BB = fma2(T1, W1.y, BB);                  \
    }

#pragma unroll 4
    for (int h2 = 0; h2 < H / 2; ++h2) {
        ull R0 = rp0[h2], R1 = rp1[h2];
        ull L0 = lp0[h2], L1 = lp1[h2];
        ulonglong2 W0 = wq[2 * h2];
        ulonglong2 W1 = wq[2 * h2 + 1];
        COMBO2(R0, L0, a00A, a00B);
        COMBO2(R0, L1, a01A, a01B);
        COMBO2(R1, L0, a10A, a10B);
        COMBO2(R1, L1, a11A, a11B);
    }
    __syncthreads();   // done reading r_s/l_s

    float4* S = (float4*)&r_s[0][0];    // 32 x 33 float4 aliases r_s
    {
        float s0, s1, s2, s3;
        unpack2(a00A, s0, s1); unpack2(a00B, s2, s3);
        S[ty * 33 + tx]             = make_float4(s0, s1, s2, s3);
        unpack2(a01A, s0, s1); unpack2(a01B, s2, s3);
        S[ty * 33 + tx + 16]        = make_float4(s0, s1, s2, s3);
        unpack2(a10A, s0, s1); unpack2(a10B, s2, s3);
        S[(ty + 16) * 33 + tx]      = make_float4(s0, s1, s2, s3);
        unpack2(a11A, s0, s1); unpack2(a11B, s2, s3);
        S[(ty + 16) * 33 + tx + 16] = make_float4(s0, s1, s2, s3);
    }
    __syncthreads();

    const float cb = conv_b[0];
    float m = -3.4e38f;
#pragma unroll
    for (int dy = 0; dy < 2; ++dy) {
#pragma unroll
        for (int dx = 0; dx < 2; ++dx) {
            int pp = ty + dy * 16, qq = tx + dx * 16;
            int p = i0 + pp, q = j0 + qq;
            if (pp < TS && qq < TS && p < L && q < L) {
                float4 a  = S[pp * 33 + qq];             // S00(p-1,q-1)
                float4 bq = S[pp * 33 + qq + 1];         // S01(p-1,q)
                float4 c  = S[(pp + 1) * 33 + qq];       // S10(p,q-1)
                float4 d  = S[(pp + 1) * 33 + qq + 1];   // S11(p,q)
                float y = cb + a.x + bq.y + c.z + d.w;
                m = fmaxf(m, y);
            }
        }
    }

#pragma unroll
    for (int o = 16; o > 0; o >>= 1)
        m = fmaxf(m, __shfl_xor_sync(0xffffffffu, m, o));
    float* red = &l_s[0][0];
    int wid = t >> 5, lid = t & 31;
    if (lid == 0) red[wid] = m;
    __syncthreads();
    if (t < 32) {
        float v = (t < 8) ? red[t] : -3.4e38f;
#pragma unroll
        for (int o = 4; o > 0; o >>= 1)
            v = fmaxf(v, __shfl_xor_sync(0xffffffffu, v, o));
        if (t == 0) {
            atomicMax(&g_maxu[b], fenc(v));
            __threadfence();
            int done = atomicAdd(&g_done, 1);
            if (done == NBLK - 1) {
#pragma unroll
                for (int bb = 0; bb < B; ++bb) {
                    unsigned u = atomicMax(&g_maxu[bb], 0u);  // atomic read
                    float mm = fdec(u);
                    out[bb] = 1.f / (1.f + expf(-mm));
                }
            }
        }
    }
}

// ---------------------------------------------------------------------------
extern "C" void kernel_launch(void* const* d_in, const int* in_sizes, int n_in,
                              void* d_out, int out_size)
{
    const float *rec = 0, *lig = 0, *W1 = 0, *b1 = 0, *conv_w = 0, *conv_b = 0;
    for (int i = 0; i < n_in; ++i) {
        int n = in_sizes[i];
        const float* p = (const float*)d_in[i];
        if (n == B * L * E)      { if (!rec) rec = p; else lig = p; }
        else if (n == E * H)     W1 = p;
        else if (n == H)         b1 = p;
        else if (n == H * 4)     conv_w = p;
        else if (n == 1)         conv_b = p;
    }
    float* out = (float*)d_out;

    gemm_tc_kernel<<<(2 * NR / 64) * 2, 256>>>(rec, lig, W1, b1);
    dim3 g2(NTILE, NTILE, B);  // 17 x 17 x 4
    tile_max_kernel<<<g2, dim3(16, 16)>>>(conv_w, conv_b, out);
}

// round 13
// speedup vs baseline: 1.0045x; 1.0045x over previous
#include <cuda_runtime.h>
#include <cuda_bf16.h>

// Problem constants
#define B 4
#define L 512
#define E 1024
#define H 128
#define NR (B * L)          // 2048 rows per tensor

__device__ __align__(16) float g_hid[2 * NR * H];
__device__ unsigned g_maxu[B];
__device__ int g_done;

typedef unsigned long long ull;

__device__ __forceinline__ float tanh_ap(float x) {
    float y;
    asm("tanh.approx.f32 %0, %1;" : "=f"(y) : "f"(x));
    return y;
}
__device__ __forceinline__ ull pack2(float lo, float hi) {
    ull r; asm("mov.b64 %0, {%1, %2};" : "=l"(r) : "f"(lo), "f"(hi)); return r;
}
__device__ __forceinline__ void unpack2(ull v, float& lo, float& hi) {
    asm("mov.b64 {%0, %1}, %2;" : "=f"(lo), "=f"(hi) : "l"(v));
}
__device__ __forceinline__ ull mul2(ull a, ull b) {
    ull r; asm("mul.rn.f32x2 %0, %1, %2;" : "=l"(r) : "l"(a), "l"(b)); return r;
}
__device__ __forceinline__ ull fma2(ull a, ull b, ull c) {
    ull r; asm("fma.rn.f32x2 %0, %1, %2, %3;" : "=l"(r) : "l"(a), "l"(b), "l"(c)); return r;
}
__device__ __forceinline__ unsigned tf32r(float x) {
    unsigned u;
    asm("cvt.rna.tf32.f32 %0, %1;" : "=r"(u) : "f"(x));
    return u;
}

__device__ __forceinline__ unsigned fenc(float f) {
    unsigned b = __float_as_uint(f);
    return (b & 0x80000000u) ? ~b : (b | 0x80000000u);
}
__device__ __forceinline__ float fdec(unsigned u) {
    return (u & 0x80000000u) ? __uint_as_float(u & 0x7fffffffu)
                             : __uint_as_float(~u);
}

// m16n8k8 tf32 MMA, f32 accumulate
__device__ __forceinline__ void mma_tf32(float c[4], const unsigned a[4],
                                         const unsigned b[2]) {
    asm volatile(
        "mma.sync.aligned.m16n8k8.row.col.f32.tf32.tf32.f32 "
        "{%0,%1,%2,%3}, {%4,%5,%6,%7}, {%8,%9}, {%0,%1,%2,%3};"
        : "+f"(c[0]), "+f"(c[1]), "+f"(c[2]), "+f"(c[3])
        : "r"(a[0]), "r"(a[1]), "r"(a[2]), "r"(a[3]),
          "r"(b[0]), "r"(b[1]));
}

// ---------------------------------------------------------------------------
// Kernel 1: hid = relu(emb @ W1 + b1) on the tensor pipe (tf32 mma.sync).
// (Unchanged — proven.)
// ---------------------------------------------------------------------------
#define KC 32
#define NTK (E / KC)     // 32 tiles
#define APAD 36
#define WPAD 72

__global__ __launch_bounds__(256) void gemm_tc_kernel(
    const float* __restrict__ rec, const float* __restrict__ lig,
    const float* __restrict__ W1, const float* __restrict__ b1)
{
    __shared__ __align__(16) float A_s[2][64][APAD];
    __shared__ __align__(16) float W_s[2][KC][WPAD];

    const int t    = threadIdx.x;
    const int bx   = blockIdx.x;
    const int row0 = (bx >> 1) * 64;
    const int col0 = (bx & 1) * 64;

    if (bx == 0 && t == 0) {
        g_done = 0;
#pragma unroll
        for (int b = 0; b < B; ++b) g_maxu[b] = 0u;
    }

    const int wid  = t >> 5;
    const int lane = t & 31;
    const int qr   = lane >> 2;        // 0..7
    const int qk   = lane & 3;         // 0..3
    const int wr   = (wid >> 2) * 32;
    const int wc   = (wid & 3) * 16;

    const int lar = t >> 2, lak = (t & 3) * 8;
    const float* aptr;
    {
        int gr = row0 + lar;
        aptr = (gr < NR) ? (rec + (size_t)gr * E + lak)
                         : (lig + (size_t)(gr - NR) * E + lak);
    }
    const int lwk = t >> 3, lwn = (t & 7) * 8;
    const float* wptr = W1 + (size_t)lwk * H + col0 + lwn;

    float4 aR0, aR1, wR0, wR1;
    float c[2][2][4];
#pragma unroll
    for (int m = 0; m < 2; ++m)
#pragma unroll
        for (int n = 0; n < 2; ++n)
#pragma unroll
            for (int i = 0; i < 4; ++i) c[m][n][i] = 0.f;

#define LDG_TILE(k0)                                         \
    {                                                        \
        aR0 = *(const float4*)(aptr + (k0));                 \
        aR1 = *(const float4*)(aptr + (k0) + 4);             \
        wR0 = *(const float4*)(wptr + (size_t)(k0) * H);     \
        wR1 = *(const float4*)(wptr + (size_t)(k0) * H + 4); \
    }
#define STS_TILE(buf)                                                     \
    {                                                                     \
        uint4 ua0 = make_uint4(tf32r(aR0.x), tf32r(aR0.y),                \
                               tf32r(aR0.z), tf32r(aR0.w));               \
        uint4 ua1 = make_uint4(tf32r(aR1.x), tf32r(aR1.y),                \
                               tf32r(aR1.z), tf32r(aR1.w));               \
        uint4 uw0 = make_uint4(tf32r(wR0.x), tf32r(wR0.y),                \
                               tf32r(wR0.z), tf32r(wR0.w));               \
        uint4 uw1 = make_uint4(tf32r(wR1.x), tf32r(wR1.y),                \
                               tf32r(wR1.z), tf32r(wR1.w));               \
        *(uint4*)&A_s[buf][lar][lak]     = ua0;                           \
        *(uint4*)&A_s[buf][lar][lak + 4] = ua1;                           \
        *(uint4*)&W_s[buf][lwk][lwn]     = uw0;                           \
        *(uint4*)&W_s[buf][lwk][lwn + 4] = uw1;                           \
    }

    LDG_TILE(0);
    STS_TILE(0);
    LDG_TILE(KC);
    __syncthreads();

    for (int kt = 0; kt < NTK; ++kt) {
        int cur = kt & 1;
#pragma unroll
        for (int ks = 0; ks < KC / 8; ++ks) {
            int k0 = ks * 8;
            unsigned a[2][4], bb[2][2];
#pragma unroll
            for (int m = 0; m < 2; ++m) {
                int r = wr + m * 16 + qr;
                a[m][0] = __float_as_uint(A_s[cur][r][k0 + qk]);
                a[m][1] = __float_as_uint(A_s[cur][r + 8][k0 + qk]);
                a[m][2] = __float_as_uint(A_s[cur][r][k0 + qk + 4]);
                a[m][3] = __float_as_uint(A_s[cur][r + 8][k0 + qk + 4]);
            }
#pragma unroll
            for (int n = 0; n < 2; ++n) {
                int nn = wc + n * 8 + qr;
                bb[n][0] = __float_as_uint(W_s[cur][k0 + qk][nn]);
                bb[n][1] = __float_as_uint(W_s[cur][k0 + qk + 4][nn]);
            }
            mma_tf32(c[0][0], a[0], bb[0]);
            mma_tf32(c[0][1], a[0], bb[1]);
            mma_tf32(c[1][0], a[1], bb[0]);
            mma_tf32(c[1][1], a[1], bb[1]);
        }
        if (kt + 1 < NTK) {
            STS_TILE(cur ^ 1);
            if (kt + 2 < NTK) LDG_TILE((kt + 2) * KC);
        }
        __syncthreads();
    }

#pragma unroll
    for (int m = 0; m < 2; ++m) {
#pragma unroll
        for (int n = 0; n < 2; ++n) {
            int row = row0 + wr + m * 16 + qr;
            int col = col0 + wc + n * 8 + 2 * qk;
            float2 bv = *(const float2*)(b1 + col);
            float2 o0, o1;
            o0.x = fmaxf(c[m][n][0] + bv.x, 0.f);
            o0.y = fmaxf(c[m][n][1] + bv.y, 0.f);
            o1.x = fmaxf(c[m][n][2] + bv.x, 0.f);
            o1.y = fmaxf(c[m][n][3] + bv.y, 0.f);
            *(float2*)&g_hid[(size_t)row * H + col]       = o0;
            *(float2*)&g_hid[(size_t)(row + 8) * H + col] = o1;
        }
    }
}

// ---------------------------------------------------------------------------
// Kernel 2: back to the R9 shape (32x32 S-tile, 2x2 micro-tile, 16x16 thr),
// but with an h2-step inner loop (half the live R/L/W registers) and
// __launch_bounds__(256, 4) to get 4 blocks/SM (occ 32% -> 50%) so the
// MUFU (tanh) pipe stays saturated.
// ---------------------------------------------------------------------------
#define TS 31
#define NTILE ((L + TS - 1) / TS)            // 17
#define NBLK  (NTILE * NTILE * B)            // 1156
#define LPAD 132

__global__ __launch_bounds__(256, 4) void tile_max_kernel(
    const float* __restrict__ conv_w, const float* __restrict__ conv_b,
    float* __restrict__ out)
{
    __shared__ __align__(16) float r_s[32][LPAD];   // 16896 B (aliased by S)
    __shared__ __align__(16) float l_s[32][LPAD];   // 16896 B
    __shared__ __align__(16) float4 w4_s[H];        // 2 KB

    const int tx = threadIdx.x;          // 0..15
    const int ty = threadIdx.y;          // 0..15
    const int t  = ty * 16 + tx;
    const int b  = blockIdx.z;
    const int i0 = blockIdx.y * TS;
    const int j0 = blockIdx.x * TS;

    {
        int lr  = t >> 3;          // 0..31 row
        int lc4 = t & 7;           // base float4 col
        int iload = i0 - 1 + lr;
        int jload = j0 - 1 + lr;
        const float4* rsrc = (const float4*)(g_hid + (size_t)(b * L + iload) * H);
        const float4* lsrc = (const float4*)(g_hid + (size_t)(NR + b * L + jload) * H);
        bool rok = (iload >= 0 && iload < L);
        bool lok = (jload >= 0 && jload < L);
        float4 zz = make_float4(0.f, 0.f, 0.f, 0.f);
        float4* rdst = (float4*)&r_s[lr][0];
        float4* ldst = (float4*)&l_s[lr][0];
#pragma unroll
        for (int k = 0; k < 4; ++k) {
            int c4 = lc4 + 8 * k;
            rdst[c4] = rok ? rsrc[c4] : zz;
            ldst[c4] = lok ? lsrc[c4] : zz;
        }
        if (t < H) w4_s[t] = ((const float4*)conv_w)[t];   // (w00,w01,w10,w11)
    }
    __syncthreads();

    ull a00A = 0, a00B = 0, a01A = 0, a01B = 0;
    ull a10A = 0, a10B = 0, a11A = 0, a11B = 0;
    const ull* rp0 = (const ull*)&r_s[ty][0];
    const ull* rp1 = (const ull*)&r_s[ty + 16][0];
    const ull* lp0 = (const ull*)&l_s[tx][0];
    const ull* lp1 = (const ull*)&l_s[tx + 16][0];
    const ulonglong2* wq = (const ulonglong2*)&w4_s[0];   // wq[h] = taps of h

    // One h2 step = 2 h values; W0/W1 are each h's (w00,w01 | w10,w11) pairs.
#define COMBO2(Rv, Lv, AA, BB)                                             \
    {                                                                      \
        ull pA = mul2(Rv, Lv);                                             \
        float x0, x1;                                                      \
        unpack2(pA, x0, x1);                                               \
        float t0 = tanh_ap(x0), t1 = tanh_ap(x1);                          \
        ull T0 = pack2(t0, t0), T1 = pack2(t1, t1);                        \
        AA = fma2(T0, W0.x, AA); BB = fma2(T0, W0.y, BB);                  \
        AA = fma2(T1, W1.x, AA); BB = fma2(T1, W1.y, BB);                  \
    }

#pragma unroll 4
    for (int h2 = 0; h2 < H / 2; ++h2) {
        ull R0 = rp0[h2], R1 = rp1[h2];
        ull L0 = lp0[h2], L1 = lp1[h2];
        ulonglong2 W0 = wq[2 * h2];
        ulonglong2 W1 = wq[2 * h2 + 1];
        COMBO2(R0, L0, a00A, a00B);
        COMBO2(R0, L1, a01A, a01B);
        COMBO2(R1, L0, a10A, a10B);
        COMBO2(R1, L1, a11A, a11B);
    }
    __syncthreads();   // done reading r_s/l_s

    float4* S = (float4*)&r_s[0][0];    // 32 x 33 float4 aliases r_s
    {
        float s0, s1, s2, s3;
        unpack2(a00A, s0, s1); unpack2(a00B, s2, s3);
        S[ty * 33 + tx]             = make_float4(s0, s1, s2, s3);
        unpack2(a01A, s0, s1); unpack2(a01B, s2, s3);
        S[ty * 33 + tx + 16]        = make_float4(s0, s1, s2, s3);
        unpack2(a10A, s0, s1); unpack2(a10B, s2, s3);
        S[(ty + 16) * 33 + tx]      = make_float4(s0, s1, s2, s3);
        unpack2(a11A, s0, s1); unpack2(a11B, s2, s3);
        S[(ty + 16) * 33 + tx + 16] = make_float4(s0, s1, s2, s3);
    }
    __syncthreads();

    const float cb = conv_b[0];
    float m = -3.4e38f;
#pragma unroll
    for (int dy = 0; dy < 2; ++dy) {
#pragma unroll
        for (int dx = 0; dx < 2; ++dx) {
            int pp = ty + dy * 16, qq = tx + dx * 16;
            int p = i0 + pp, q = j0 + qq;
            if (pp < TS && qq < TS && p < L && q < L) {
                float4 a  = S[pp * 33 + qq];             // S00(p-1,q-1)
                float4 bq = S[pp * 33 + qq + 1];         // S01(p-1,q)
                float4 c  = S[(pp + 1) * 33 + qq];       // S10(p,q-1)
                float4 d  = S[(pp + 1) * 33 + qq + 1];   // S11(p,q)
                float y = cb + a.x + bq.y + c.z + d.w;
                m = fmaxf(m, y);
            }
        }
    }

#pragma unroll
    for (int o = 16; o > 0; o >>= 1)
        m = fmaxf(m, __shfl_xor_sync(0xffffffffu, m, o));
    float* red = &l_s[0][0];
    int wid = t >> 5, lid = t & 31;
    if (lid == 0) red[wid] = m;
    __syncthreads();
    if (t < 32) {
        float v = (t < 8) ? red[t] : -3.4e38f;
#pragma unroll
        for (int o = 4; o > 0; o >>= 1)
            v = fmaxf(v, __shfl_xor_sync(0xffffffffu, v, o));
        if (t == 0) {
            atomicMax(&g_maxu[b], fenc(v));
            __threadfence();
            int done = atomicAdd(&g_done, 1);
            if (done == NBLK - 1) {
#pragma unroll
                for (int bb = 0; bb < B; ++bb) {
                    unsigned u = atomicMax(&g_maxu[bb], 0u);  // atomic read
                    float mm = fdec(u);
                    out[bb] = 1.f / (1.f + expf(-mm));
                }
            }
        }
    }
}

// ---------------------------------------------------------------------------
extern "C" void kernel_launch(void* const* d_in, const int* in_sizes, int n_in,
                              void* d_out, int out_size)
{
    const float *rec = 0, *lig = 0, *W1 = 0, *b1 = 0, *conv_w = 0, *conv_b = 0;
    for (int i = 0; i < n_in; ++i) {
        int n = in_sizes[i];
        const float* p = (const float*)d_in[i];
        if (n == B * L * E)      { if (!rec) rec = p; else lig = p; }
        else if (n == E * H)     W1 = p;
        else if (n == H)         b1 = p;
        else if (n == H * 4)     conv_w = p;
        else if (n == 1)         conv_b = p;
    }
    float* out = (float*)d_out;

    gemm_tc_kernel<<<(2 * NR / 64) * 2, 256>>>(rec, lig, W1, b1);
    dim3 g2(NTILE, NTILE, B);  // 17 x 17 x 4
    tile_max_kernel<<<g2, dim3(16, 16)>>>(conv_w, conv_b, out);
}